// round 1
// baseline (speedup 1.0000x reference)
#include <cuda_runtime.h>
#include <cuda_bf16.h>

#define TSTEPS 400
#define CHUNK  16
#define NCHUNK 25   // 25 * 16 = 400

// Exact reference simulation for rare rows (trailing run >= 16 or fewer than
// 2 corrects in the first 32 steps). Matches the JAX reference op-for-op.
__device__ __noinline__ float sm2_slow_row(const float* __restrict__ row) {
    float I = 1.0f, n = 0.0f, EF = 2.5f;
    for (int t = 0; t < TSTEPS; ++t) {
        float p = row[t];
        float q = p * 5.0f;
        bool correct = (q >= 3.0f);
        bool brk = (p == -1.0f);
        float In;
        if (n >= 2.0f)      In = I * EF;
        else if (n == 1.0f) In = 6.0f;
        else                In = 1.0f;
        if (!correct) In = 1.0f;
        if (!brk) I = In;
        I = fminf(fmaxf(I, 1.0f), 274.0f);
        float d = 5.0f - q;
        EF = EF + (0.1f - d * (0.08f + d * 0.02f));
        EF = fmaxf(EF, 1.3f);
        if (correct) n += 1.0f;
    }
    return I;
}

__device__ __forceinline__ void load_chunk(const float4* __restrict__ rowv,
                                           int ch, float (&pa)[CHUNK]) {
    float4 v0 = rowv[ch * 4 + 0];
    float4 v1 = rowv[ch * 4 + 1];
    float4 v2 = rowv[ch * 4 + 2];
    float4 v3 = rowv[ch * 4 + 3];
    pa[0]=v0.x;  pa[1]=v0.y;  pa[2]=v0.z;  pa[3]=v0.w;
    pa[4]=v1.x;  pa[5]=v1.y;  pa[6]=v1.z;  pa[7]=v1.w;
    pa[8]=v2.x;  pa[9]=v2.y;  pa[10]=v2.z; pa[11]=v2.w;
    pa[12]=v3.x; pa[13]=v3.y; pa[14]=v3.z; pa[15]=v3.w;
}

__global__ void __launch_bounds__(256)
sm2_kernel(const float* __restrict__ p, float* __restrict__ out, int B) {
    int b = blockIdx.x * blockDim.x + threadIdx.x;
    if (b >= B) return;

    const float* row = p + (size_t)b * TSTEPS;
    const float4* rowv = reinterpret_cast<const float4*>(row);

    float E = 2.5f;          // EF after step t (starts as EF_{-1} = 2.5)
    float Eh[CHUNK];         // ring of last 16 E_t values (registers, static idx)
    float pa[CHUNK];         // current chunk's p values (last chunk survives loop)
    int   cnt2 = 0;          // # corrects in first 32 steps

    // Chunks 0..1: same recursion + correctness counting.
    #pragma unroll 1
    for (int ch = 0; ch < 2; ++ch) {
        load_chunk(rowv, ch, pa);
        #pragma unroll
        for (int j = 0; j < CHUNK; ++j) {
            float d  = fmaf(pa[j], -5.0f, 5.0f);   // d = 5 - 5p  (q>=3 <=> d<=2)
            float t2 = fmaf(d, 0.02f, 0.08f);
            float dl = fmaf(-d, t2, 0.1f);         // delta = 0.1 - d*(0.08+0.02d)
            E = fmaxf(E + dl, 1.3f);
            Eh[j] = E;
            cnt2 += (pa[j] * 5.0f >= 3.0f);
        }
    }

    // Chunks 2..24: hot loop, 5 ops/step.
    #pragma unroll 1
    for (int ch = 2; ch < NCHUNK; ++ch) {
        load_chunk(rowv, ch, pa);
        #pragma unroll
        for (int j = 0; j < CHUNK; ++j) {
            float d  = fmaf(pa[j], -5.0f, 5.0f);
            float t2 = fmaf(d, 0.02f, 0.08f);
            float dl = fmaf(-d, t2, 0.1f);
            E = fmaxf(E + dl, 1.3f);
            Eh[j] = E;                              // Eh[j] = E_{384+j} on last chunk
        }
    }

    // Trailing-correct mask over the last chunk (t = 384+j).
    unsigned mask = 0u;
    #pragma unroll
    for (int j = 0; j < CHUNK; ++j)
        mask |= (pa[j] * 5.0f >= 3.0f) ? (1u << j) : 0u;

    // L = length of trailing run of corrects (count of consecutive 1s from bit 15).
    int L = __clz(((~mask) & 0xFFFFu) << 16);      // mask==0xFFFF -> L=32 -> slow

    float I;
    if (L <= 15 && cnt2 >= 2) {
        // n >= 2 before the run; step r0-1 (incorrect) left I = 1.
        // Final I = min( prod_{t=399-L}^{398} E_t , 274 ); factors >= 1.3 so the
        // per-step clip equals the final clip. E_t = Eh[t-384], t in [384,399].
        float prod = 1.0f;
        #pragma unroll
        for (int j = 0; j < 15; ++j)
            if (j >= 15 - L) prod = fminf(prod * Eh[j], 274.0f);
        I = (L == 0) ? 1.0f : prod;
    } else {
        I = sm2_slow_row(row);                     // rare: ~1-3 rows in 524288
    }

    // h = clip(I / 0.5, 15/1440, 274); 2I >= 2 > OUT_MIN always.
    out[b] = fminf(2.0f * I, 274.0f);
}

extern "C" void kernel_launch(void* const* d_in, const int* in_sizes, int n_in,
                              void* d_out, int out_size) {
    const float* p = (const float*)d_in[0];
    float* out = (float*)d_out;
    int B = out_size;                // rows; in_sizes[0] == B * 400
    int threads = 256;
    int blocks = (B + threads - 1) / threads;
    sm2_kernel<<<blocks, threads>>>(p, out, B);
}